// round 16
// baseline (speedup 1.0000x reference)
#include <cuda_runtime.h>
#include <cuda_fp16.h>
#include <mma.h>
#include <cstdint>

using namespace nvcuda;

#define NN 50000
#define EE 800000
#define ET (EE + NN)
#define HEADS 4
#define HID 64
#define C1 256   /* HEADS*HID */
#define C2 64
#define NEG 0.2f
#define CH 25088 /* node chunk split (196*128) */

// ---------------- scratch (device globals; no cudaMalloc allowed) -------------
__device__ __align__(16) __half g_xh[(size_t)NN * 128];   // x (fp16)
__device__ __align__(16) __half g_h1h[(size_t)NN * C1];   // layer1 features (fp16)
__device__ __align__(16) __half g_h2h[(size_t)NN * C1];   // elu(agg1+b1) (fp16)
__device__ __align__(16) __half g_h2l[(size_t)NN * C2];   // h2 @ W2 (fp16)
__device__ __align__(16) float g_als1[NN * HEADS];
__device__ __align__(16) float g_ald1[NN * HEADS];
__device__ float g_als2[NN];
__device__ float g_ald2[NN];
__device__ int   g_cnt[NN];
__device__ int   g_off[NN + 1];
__device__ int   g_cur[NN];
__device__ int   g_psrc[ET];
__device__ int   g_bsum[256];
__device__ __align__(16) __half g_w1h[128 * C1];   // [k=128][n=256]
__device__ __align__(16) __half g_w2h[C1 * C2];    // [k=256][n=64]

__device__ __forceinline__ float lrelu(float x) { return x > 0.f ? x : NEG * x; }
__device__ __forceinline__ float elu_f(float x) { return x > 0.f ? x : __expf(x) - 1.f; }

__device__ __forceinline__ void cp16z(uint32_t d, const void* s, bool pred) {
  if (pred)
    asm volatile("cp.async.ca.shared.global [%0], [%1], 16;" :: "r"(d), "l"(s));
  else
    asm volatile("cp.async.ca.shared.global [%0], [%1], 16, 0;" :: "r"(d), "l"(s));
}
__device__ __forceinline__ void cpa_commit() {
  asm volatile("cp.async.commit_group;" ::: "memory");
}
template <int N>
__device__ __forceinline__ void cpa_wait() {
  asm volatile("cp.async.wait_group %0;" :: "n"(N) : "memory");
}

// ---------------- CSR build ---------------------------------------------------
__global__ void k_hist(const int* __restrict__ ei) {
  int e = blockIdx.x * blockDim.x + threadIdx.x;
  if (e < EE) atomicAdd(&g_cnt[ei[EE + e]], 1);
}

__global__ __launch_bounds__(256) void k_scan1() {
  int i = blockIdx.x * 256 + threadIdx.x;
  int v = 0;
  if (i < NN) { v = g_cnt[i] + 1; g_cnt[i] = 0; }
  int lane = threadIdx.x & 31, wid = threadIdx.x >> 5;
  int x = v;
#pragma unroll
  for (int o = 1; o < 32; o <<= 1) {
    int y = __shfl_up_sync(0xffffffffu, x, o);
    if (lane >= o) x += y;
  }
  __shared__ int ws[8];
  if (lane == 31) ws[wid] = x;
  __syncthreads();
  if (threadIdx.x < 8) {
    int z = ws[threadIdx.x];
#pragma unroll
    for (int o = 1; o < 8; o <<= 1) {
      int q = __shfl_up_sync(0xffu, z, o);
      if ((int)threadIdx.x >= o) z += q;
    }
    ws[threadIdx.x] = z;
  }
  __syncthreads();
  int incl = x + (wid ? ws[wid - 1] : 0);
  if (i < NN) g_off[i] = incl - v;
  if (threadIdx.x == 255) g_bsum[blockIdx.x] = incl;
}

__global__ __launch_bounds__(256) void k_scan2() {
  const int NB = (NN + 255) / 256;
  int t = threadIdx.x;
  int v = (t < NB) ? g_bsum[t] : 0;
  int lane = t & 31, wid = t >> 5;
  int x = v;
#pragma unroll
  for (int o = 1; o < 32; o <<= 1) {
    int y = __shfl_up_sync(0xffffffffu, x, o);
    if (lane >= o) x += y;
  }
  __shared__ int ws[8];
  if (lane == 31) ws[wid] = x;
  __syncthreads();
  if (t < 8) {
    int z = ws[t];
#pragma unroll
    for (int o = 1; o < 8; o <<= 1) {
      int q = __shfl_up_sync(0xffu, z, o);
      if (t >= o) z += q;
    }
    ws[t] = z;
  }
  __syncthreads();
  int incl = x + (wid ? ws[wid - 1] : 0);
  if (t < NB) g_bsum[t] = incl - v;
}

__global__ void k_scan3() {
  int i = blockIdx.x * blockDim.x + threadIdx.x;
  if (i < NN) {
    int o = g_off[i] + g_bsum[i >> 8];
    g_off[i] = o;
    g_psrc[o] = i;
    g_cur[i] = o + 1;
  }
  if (i == 0) g_off[NN] = ET;
}

__global__ void k_scatter(const int* __restrict__ ei) {
  int e = blockIdx.x * blockDim.x + threadIdx.x;
  if (e < EE) {
    int s = ei[e];
    int d = ei[EE + e];
    g_psrc[atomicAdd(&g_cur[d], 1)] = s;
  }
}

// ---------------- conversions ---------------------------------------------------
__global__ void k_cvtx(const float* __restrict__ x) {
  int i = blockIdx.x * blockDim.x + threadIdx.x;   // 8-elem chunk index
  const int n8 = NN * 128 / 8;
  if (i >= n8) return;
  float4 v0 = __ldg((const float4*)x + 2 * i);
  float4 v1 = __ldg((const float4*)x + 2 * i + 1);
  union Pk { __half h[8]; uint4 u; } pk;
  pk.h[0] = __float2half_rn(v0.x); pk.h[1] = __float2half_rn(v0.y);
  pk.h[2] = __float2half_rn(v0.z); pk.h[3] = __float2half_rn(v0.w);
  pk.h[4] = __float2half_rn(v1.x); pk.h[5] = __float2half_rn(v1.y);
  pk.h[6] = __float2half_rn(v1.z); pk.h[7] = __float2half_rn(v1.w);
  ((uint4*)g_xh)[i] = pk.u;
}

__global__ void k_cvtw(const float* __restrict__ W1, const float* __restrict__ W2) {
  int i = blockIdx.x * blockDim.x + threadIdx.x;
  if (i < 128 * 256) g_w1h[i] = __float2half_rn(__ldg(&W1[i]));
  if (i < 256 * 64)  g_w2h[i] = __float2half_rn(__ldg(&W2[i]));
}

// ---------------- wmma GEMM (fp16 x fp16, fp32 accum, all-cp.async) ------------
template <int MODE>
__global__ __launch_bounds__(256, 2) void k_wgemm(const float* __restrict__ avs,
                                                  const float* __restrict__ avd,
                                                  int bmb) {
  constexpr int K  = (MODE == 1) ? 128 : 256;
  constexpr int NC = (MODE == 1) ? 256 : 64;
  constexpr int BN = (MODE == 1) ? 128 : 64;
  constexpr int BM = 128, BK = 32;
  constexpr int KT = K / BK;
  constexpr int LDA = 40;         // 80 B rows — conflict-free
  constexpr int LDB = BN + 8;     // 272/144 B rows — conflict-free
  constexpr int NJ = BN / 32;
  constexpr int ASTG = BM * LDA;
  constexpr int BSTG = BK * LDB;
  constexpr int LDC = BN + 4;

  extern __shared__ __half sm[];
  __half* Ah = sm;                      // [2][ASTG]
  __half* Bh = Ah + 2 * ASTG;           // [2][BSTG]
  float* Ct = (float*)sm;               // overlay after MMA

  const __half* Ag = (MODE == 1) ? g_xh : g_h2h;
  const __half* Bg = (MODE == 1) ? g_w1h : g_w2h;

  const int tid = threadIdx.x;
  const int wid = tid >> 5;
  const int lane = tid & 31;
  const int wr = wid >> 1, wc = wid & 1;
  const int bm = (blockIdx.x + bmb) * BM;
  const int bn = blockIdx.y * BN;

  auto loadA = [&](int kt, int st) {
#pragma unroll
    for (int it = 0; it < 2; it++) {
      int v = it * 256 + tid;
      int r = v >> 2, c8 = (v & 3) << 3;
      int gr = bm + r;
      bool ok = gr < NN;
      size_t go = (size_t)(ok ? gr : 0) * K + kt * BK + c8;
      cp16z((uint32_t)__cvta_generic_to_shared(&Ah[st * ASTG + r * LDA + c8]),
            Ag + go, ok);
    }
  };
  auto loadB = [&](int kt, int st) {
    constexpr int NV = BK * BN / 8;
#pragma unroll
    for (int it = 0; it < NV / 256; it++) {
      int v = it * 256 + tid;
      int r = v / (BN / 8), c8 = (v % (BN / 8)) << 3;
      size_t go = (size_t)(kt * BK + r) * NC + bn + c8;
      cp16z((uint32_t)__cvta_generic_to_shared(&Bh[st * BSTG + r * LDB + c8]),
            Bg + go, true);
    }
  };

  wmma::fragment<wmma::accumulator, 16, 16, 16, float> acc[2][NJ];
#pragma unroll
  for (int i = 0; i < 2; i++)
#pragma unroll
    for (int j = 0; j < NJ; j++) wmma::fill_fragment(acc[i][j], 0.f);

  loadA(0, 0); loadB(0, 0); cpa_commit();
  cpa_wait<0>();
  __syncthreads();

#pragma unroll
  for (int kt = 0; kt < KT; kt++) {
    const int cur = kt & 1;
    const bool pre = (kt + 1 < KT);
    if (pre) { loadA(kt + 1, cur ^ 1); loadB(kt + 1, cur ^ 1); cpa_commit(); }
#pragma unroll
    for (int kk = 0; kk < BK; kk += 16) {
      wmma::fragment<wmma::matrix_a, 16, 16, 16, __half, wmma::row_major> fa[2];
#pragma unroll
      for (int i = 0; i < 2; i++)
        wmma::load_matrix_sync(fa[i], &Ah[cur * ASTG + (wr * 32 + i * 16) * LDA + kk], LDA);
#pragma unroll
      for (int j = 0; j < NJ; j++) {
        wmma::fragment<wmma::matrix_b, 16, 16, 16, __half, wmma::row_major> fb;
        wmma::load_matrix_sync(fb, &Bh[cur * BSTG + kk * LDB + wc * NJ * 16 + j * 16], LDB);
        wmma::mma_sync(acc[0][j], fa[0], fb, acc[0][j]);
        wmma::mma_sync(acc[1][j], fa[1], fb, acc[1][j]);
      }
    }
    if (pre) cpa_wait<0>();
    __syncthreads();
  }

#pragma unroll
  for (int i = 0; i < 2; i++)
#pragma unroll
    for (int j = 0; j < NJ; j++)
      wmma::store_matrix_sync(&Ct[(wr * 32 + i * 16) * LDC + wc * NJ * 16 + j * 16],
                              acc[i][j], LDC, wmma::mem_row_major);
  __syncthreads();

  // write C as fp16 (g_h1h for MODE1, g_h2l for MODE2)
  {
    __half* dst = (MODE == 1) ? g_h1h : g_h2l;
    constexpr int NV8 = BM * BN / 8;
    for (int v = tid; v < NV8; v += 256) {
      int r = v / (BN / 8), c8 = (v % (BN / 8)) << 3;
      if (bm + r < NN) {
        const float* src = &Ct[r * LDC + c8];
        union Pk { __half h[8]; uint4 u; } pk;
#pragma unroll
        for (int e = 0; e < 8; e++) pk.h[e] = __float2half_rn(src[e]);
        *(uint4*)&dst[(size_t)(bm + r) * NC + bn + c8] = pk.u;
      }
    }
  }

  const int rl = wid * 16 + (lane >> 1);
  const int hl = lane & 1;
  const int row = bm + rl;
  if constexpr (MODE == 1) {
    if (row < NN) {
      const float* cr = &Ct[rl * LDC + hl * 64];
      const float* va2 = avs + (blockIdx.y * 2 + hl) * 64;
      const float* vd2 = avd + (blockIdx.y * 2 + hl) * 64;
      float ss = 0.f, dd = 0.f;
#pragma unroll
      for (int t = 0; t < 64; t += 4) {
        float4 c = *(const float4*)(cr + t);
        float4 a = __ldg((const float4*)(va2 + t));
        float4 d = __ldg((const float4*)(vd2 + t));
        ss += c.x * a.x + c.y * a.y + c.z * a.z + c.w * a.w;
        dd += c.x * d.x + c.y * d.y + c.z * d.z + c.w * d.w;
      }
      g_als1[row * 4 + blockIdx.y * 2 + hl] = ss;
      g_ald1[row * 4 + blockIdx.y * 2 + hl] = dd;
    }
  } else {
    const float* cr = &Ct[rl * LDC + hl * 32];
    float ss = 0.f, dd = 0.f;
#pragma unroll
    for (int t = 0; t < 32; t += 4) {
      float4 c = *(const float4*)(cr + t);
      float4 a = __ldg((const float4*)(avs + hl * 32 + t));
      float4 d = __ldg((const float4*)(avd + hl * 32 + t));
      ss += c.x * a.x + c.y * a.y + c.z * a.z + c.w * a.w;
      dd += c.x * d.x + c.y * d.y + c.z * d.z + c.w * d.w;
    }
    ss += __shfl_xor_sync(0xffffffffu, ss, 1);
    dd += __shfl_xor_sync(0xffffffffu, dd, 1);
    if (hl == 0 && row < NN) {
      g_als2[row] = ss;
      g_ald2[row] = dd;
    }
  }
}

// ---------------- layer1 aggregation: warp per node, 2 edge-groups -------------
__global__ __launch_bounds__(256) void k_agg1(const float* __restrict__ b1,
                                              int n0, int n1) {
  int w = n0 + ((blockIdx.x * 256 + threadIdx.x) >> 5);
  int lane = threadIdx.x & 31;
  if (w >= n1) return;
  const int node = w;
  const int off = g_off[node], end = g_off[node + 1];
  float4 ad = *(const float4*)&g_ald1[node * 4];

  // ---- softmax stats: all 32 lanes over edges ----
  float m0 = -3e38f, m1 = -3e38f, m2 = -3e38f, m3 = -3e38f;
  float s0 = 0.f, s1 = 0.f, s2 = 0.f, s3 = 0.f;
  for (int j = off + lane; j < end; j += 32) {
    int s = g_psrc[j];
    float4 as = __ldg((const float4*)&g_als1[s * 4]);
    float e0 = lrelu(as.x + ad.x), e1 = lrelu(as.y + ad.y);
    float e2 = lrelu(as.z + ad.z), e3 = lrelu(as.w + ad.w);
    float n0_ = fmaxf(m0, e0), n1_ = fmaxf(m1, e1);
    float n2_ = fmaxf(m2, e2), n3_ = fmaxf(m3, e3);
    s0 = s0 * __expf(m0 - n0_) + __expf(e0 - n0_); m0 = n0_;
    s1 = s1 * __expf(m1 - n1_) + __expf(e1 - n1_); m1 = n1_;
    s2 = s2 * __expf(m2 - n2_) + __expf(e2 - n2_); m2 = n2_;
    s3 = s3 * __expf(m3 - n3_) + __expf(e3 - n3_); m3 = n3_;
  }
  float lm0 = m0, lm1 = m1, lm2 = m2, lm3 = m3;
#pragma unroll
  for (int o = 16; o; o >>= 1) {
    m0 = fmaxf(m0, __shfl_xor_sync(0xffffffffu, m0, o));
    m1 = fmaxf(m1, __shfl_xor_sync(0xffffffffu, m1, o));
    m2 = fmaxf(m2, __shfl_xor_sync(0xffffffffu, m2, o));
    m3 = fmaxf(m3, __shfl_xor_sync(0xffffffffu, m3, o));
  }
  s0 *= __expf(lm0 - m0);
  s1 *= __expf(lm1 - m1);
  s2 *= __expf(lm2 - m2);
  s3 *= __expf(lm3 - m3);
#pragma unroll
  for (int o = 16; o; o >>= 1) {
    s0 += __shfl_xor_sync(0xffffffffu, s0, o);
    s1 += __shfl_xor_sync(0xffffffffu, s1, o);
    s2 += __shfl_xor_sync(0xffffffffu, s2, o);
    s3 += __shfl_xor_sync(0xffffffffu, s3, o);
  }

  // ---- weighted gather: 2 edge-groups x 16 lanes x 16 channels ----
  const int half = lane >> 4;       // edge group
  const int li = lane & 15;
  const int c0 = li << 4;           // 16 channels per lane
  const int hd = li >> 2;           // head of my channels
  float mh = hd == 0 ? m0 : hd == 1 ? m1 : hd == 2 ? m2 : m3;
  float sh = hd == 0 ? s0 : hd == 1 ? s1 : hd == 2 ? s2 : s3;
  float adh = hd == 0 ? ad.x : hd == 1 ? ad.y : hd == 2 ? ad.z : ad.w;
  float inv = 1.f / (sh + 1e-16f);

  float acc[16];
#pragma unroll
  for (int e = 0; e < 16; e++) acc[e] = 0.f;

  int j = off + half;
  int sA = 0, sB = 0;
  if (j < end) sA = g_psrc[j];
  if (j + 2 < end) sB = g_psrc[j + 2];
  while (j + 2 < end) {
    int nA = (j + 4 < end) ? g_psrc[j + 4] : 0;
    int nB = (j + 6 < end) ? g_psrc[j + 6] : 0;
    float aA = __ldg(&g_als1[sA * 4 + hd]);
    float aB = __ldg(&g_als1[sB * 4 + hd]);
    const uint4* pA = (const uint4*)(g_h1h + (size_t)sA * C1 + c0);
    const uint4* pB = (const uint4*)(g_h1h + (size_t)sB * C1 + c0);
    uint4 uA0 = __ldg(pA), uA1 = __ldg(pA + 1);
    uint4 uB0 = __ldg(pB), uB1 = __ldg(pB + 1);
    float alA = __expf(lrelu(aA + adh) - mh) * inv;
    float alB = __expf(lrelu(aB + adh) - mh) * inv;
    const __half2* hA0 = (const __half2*)&uA0;
    const __half2* hA1 = (const __half2*)&uA1;
    const __half2* hB0 = (const __half2*)&uB0;
    const __half2* hB1 = (const __half2*)&uB1;
#pragma unroll
    for (int q = 0; q < 4; q++) {
      float2 a0 = __half22float2(hA0[q]);
      float2 a1 = __half22float2(hA1[q]);
      float2 b0 = __half22float2(hB0[q]);
      float2 b1v = __half22float2(hB1[q]);
      acc[2 * q]         += a0.x * alA + b0.x * alB;
      acc[2 * q + 1]     += a0.y * alA + b0.y * alB;
      acc[8 + 2 * q]     += a1.x * alA + b1v.x * alB;
      acc[8 + 2 * q + 1] += a1.y * alA + b1v.y * alB;
    }
    j += 4; sA = nA; sB = nB;
  }
  if (j < end) {
    float aA = __ldg(&g_als1[sA * 4 + hd]);
    const uint4* pA = (const uint4*)(g_h1h + (size_t)sA * C1 + c0);
    uint4 uA0 = __ldg(pA), uA1 = __ldg(pA + 1);
    float alA = __expf(lrelu(aA + adh) - mh) * inv;
    const __half2* hA0 = (const __half2*)&uA0;
    const __half2* hA1 = (const __half2*)&uA1;
#pragma unroll
    for (int q = 0; q < 4; q++) {
      float2 a0 = __half22float2(hA0[q]);
      float2 a1 = __half22float2(hA1[q]);
      acc[2 * q]         += a0.x * alA;
      acc[2 * q + 1]     += a0.y * alA;
      acc[8 + 2 * q]     += a1.x * alA;
      acc[8 + 2 * q + 1] += a1.y * alA;
    }
  }
  // combine edge-groups
#pragma unroll
  for (int e = 0; e < 16; e++)
    acc[e] += __shfl_xor_sync(0xffffffffu, acc[e], 16);

  if (half == 0) {
    float4 bb0 = __ldg((const float4*)&b1[c0]);
    float4 bb1 = __ldg((const float4*)&b1[c0 + 4]);
    float4 bb2 = __ldg((const float4*)&b1[c0 + 8]);
    float4 bb3 = __ldg((const float4*)&b1[c0 + 12]);
    float bb[16] = {bb0.x, bb0.y, bb0.z, bb0.w, bb1.x, bb1.y, bb1.z, bb1.w,
                    bb2.x, bb2.y, bb2.z, bb2.w, bb3.x, bb3.y, bb3.z, bb3.w};
    union Pk { __half h[8]; uint4 u; } p0, p1;
#pragma unroll
    for (int e = 0; e < 8; e++) {
      p0.h[e] = __float2half_rn(elu_f(acc[e] + bb[e]));
      p1.h[e] = __float2half_rn(elu_f(acc[8 + e] + bb[8 + e]));
    }
    uint4* dst = (uint4*)(g_h2h + (size_t)node * C1 + c0);
    dst[0] = p0.u;
    dst[1] = p1.u;
  }
}

// ---------------- layer2 aggregation: warp per dst node (fp16 gather) ---------
__global__ __launch_bounds__(256) void k_agg2(const float* __restrict__ b2,
                                              float* __restrict__ out) {
  int w = (blockIdx.x * 256 + threadIdx.x) >> 5;
  int lane = threadIdx.x & 31;
  if (w >= NN) return;
  const int node = w;
  const int off = g_off[node], end = g_off[node + 1];
  float ad = g_ald2[node];

  float m = -3e38f, su = 0.f;
  for (int j = off + lane; j < end; j += 32) {
    int s = g_psrc[j];
    float e = lrelu(__ldg(&g_als2[s]) + ad);
    float nm = fmaxf(m, e);
    su = su * __expf(m - nm) + __expf(e - nm); m = nm;
  }
  float lm = m;
#pragma unroll
  for (int o = 16; o; o >>= 1)
    m = fmaxf(m, __shfl_xor_sync(0xffffffffu, m, o));
  su *= __expf(lm - m);
#pragma unroll
  for (int o = 16; o; o >>= 1)
    su += __shfl_xor_sync(0xffffffffu, su, o);
  float inv = 1.f / (su + 1e-16f);

  float a0 = 0.f, a1 = 0.f;
  const int c = lane << 1;
  int j = off;
  int sA = 0, sB = 0;
  if (j + 2 <= end) { sA = g_psrc[j]; sB = g_psrc[j + 1]; }
  while (j + 2 <= end) {
    int nA = sA, nB = sB;
    if (j + 4 <= end) { nA = g_psrc[j + 2]; nB = g_psrc[j + 3]; }
    float eA = __ldg(&g_als2[sA]), eB = __ldg(&g_als2[sB]);
    float2 pA = __half22float2(__ldg((const __half2*)(g_h2l + (size_t)sA * C2 + c)));
    float2 pB = __half22float2(__ldg((const __half2*)(g_h2l + (size_t)sB * C2 + c)));
    float alA = __expf(lrelu(eA + ad) - m) * inv;
    float alB = __expf(lrelu(eB + ad) - m) * inv;
    a0 += pA.x * alA + pB.x * alB;
    a1 += pA.y * alA + pB.y * alB;
    j += 2; sA = nA; sB = nB;
  }
  if (j < end) {
    int s = g_psrc[j];
    float alpha = __expf(lrelu(__ldg(&g_als2[s]) + ad) - m) * inv;
    float2 p = __half22float2(__ldg((const __half2*)(g_h2l + (size_t)s * C2 + c)));
    a0 += p.x * alpha;
    a1 += p.y * alpha;
  }
  float2 r;
  r.x = elu_f(a0 + __ldg(&b2[c]));
  r.y = elu_f(a1 + __ldg(&b2[c + 1]));
  *(float2*)(out + (size_t)node * C2 + c) = r;
}

// ---------------- launch ------------------------------------------------------
extern "C" void kernel_launch(void* const* d_in, const int* in_sizes, int n_in,
                              void* d_out, int out_size) {
  const float* x = (const float*)d_in[0];
  const int* ei = (const int*)d_in[1];
  const float* W1 = (const float*)d_in[2];
  const float* as1 = (const float*)d_in[3];
  const float* ad1 = (const float*)d_in[4];
  const float* b1 = (const float*)d_in[5];
  const float* W2 = (const float*)d_in[6];
  const float* as2 = (const float*)d_in[7];
  const float* ad2 = (const float*)d_in[8];
  const float* b2 = (const float*)d_in[9];
  float* out = (float*)d_out;

  static cudaStream_t s_csr = nullptr;
  static cudaEvent_t ev_fork = nullptr, ev_join = nullptr, ev_a0 = nullptr,
                     ev_w0 = nullptr;
  if (!s_csr) {
    cudaStreamCreateWithFlags(&s_csr, cudaStreamNonBlocking);
    cudaEventCreateWithFlags(&ev_fork, cudaEventDisableTiming);
    cudaEventCreateWithFlags(&ev_join, cudaEventDisableTiming);
    cudaEventCreateWithFlags(&ev_a0, cudaEventDisableTiming);
    cudaEventCreateWithFlags(&ev_w0, cudaEventDisableTiming);
  }

  // smem = max(pipeline, C-tile overlay)
  const int PIPE1 = (2 * 128 * 40 + 2 * 32 * 136) * 2;  // 37888 B
  const int CT1 = 128 * (128 + 4) * 4;                  // 67584 B
  const int SMEM1 = PIPE1 > CT1 ? PIPE1 : CT1;
  const int PIPE2 = (2 * 128 * 40 + 2 * 32 * 72) * 2;   // 29696 B
  const int CT2 = 128 * (64 + 4) * 4;                   // 34816 B
  const int SMEM2 = PIPE2 > CT2 ? PIPE2 : CT2;
  cudaFuncSetAttribute(k_wgemm<1>, cudaFuncAttributeMaxDynamicSharedMemorySize, SMEM1);
  cudaFuncSetAttribute(k_wgemm<2>, cudaFuncAttributeMaxDynamicSharedMemorySize, SMEM2);

  const int NB = (NN + 255) / 256;  // 196
  const int NT = (NN + 127) / 128;  // 391
  const int NT0 = CH / 128;         // 196
  const int NT1 = NT - NT0;         // 195

  cudaEventRecord(ev_fork, 0);
  cudaStreamWaitEvent(s_csr, ev_fork, 0);

  // submission order: idx 3 = k_wgemm<1> (profiler captures 4th kernel)
  k_cvtx<<<(NN * 128 / 8 + 255) / 256, 256>>>(x);               // s0, idx 0
  k_cvtw<<<128, 256>>>(W1, W2);                                 // s0, idx 1
  k_hist<<<(EE + 255) / 256, 256, 0, s_csr>>>(ei);              // idx 2
  dim3 g1(NT, C1 / 128);
  k_wgemm<1><<<g1, 256, SMEM1>>>(as1, ad1, 0);                  // s0, idx 3
  k_scan1<<<NB, 256, 0, s_csr>>>();                             // idx 4
  k_scan2<<<1, 256, 0, s_csr>>>();                              // idx 5
  k_scan3<<<NB, 256, 0, s_csr>>>();                             // idx 6
  k_scatter<<<(EE + 255) / 256, 256, 0, s_csr>>>(ei);           // idx 7
  cudaEventRecord(ev_join, s_csr);

  cudaStreamWaitEvent(0, ev_join, 0);
  k_agg1<<<CH * 32 / 256, 256>>>(b1, 0, CH);                    // chunk 0
  cudaEventRecord(ev_a0, 0);
  k_agg1<<<((NN - CH) * 32 + 255) / 256, 256>>>(b1, CH, NN);    // chunk 1

  cudaStreamWaitEvent(s_csr, ev_a0, 0);
  k_wgemm<2><<<NT0, 256, SMEM2, s_csr>>>(as2, ad2, 0);
  cudaEventRecord(ev_w0, s_csr);

  k_wgemm<2><<<NT1, 256, SMEM2>>>(as2, ad2, NT0);

  cudaStreamWaitEvent(0, ev_w0, 0);
  int nwb = (NN * 32 + 255) / 256;
  k_agg2<<<nwb, 256>>>(b2, out);
}

// round 17
// speedup vs baseline: 1.0167x; 1.0167x over previous
#include <cuda_runtime.h>
#include <cuda_fp16.h>
#include <mma.h>
#include <cstdint>

using namespace nvcuda;

#define NN 50000
#define EE 800000
#define ET (EE + NN)
#define HEADS 4
#define HID 64
#define C1 256   /* HEADS*HID */
#define C2 64
#define NEG 0.2f
#define CH 25088 /* node chunk split (196*128) */

// ---------------- scratch (device globals; no cudaMalloc allowed) -------------
__device__ __align__(16) __half g_xh[(size_t)NN * 128];   // x (fp16)
__device__ __align__(16) __half g_h1h[(size_t)NN * C1];   // layer1 features (fp16)
__device__ __align__(16) __half g_h2h[(size_t)NN * C1];   // elu(agg1+b1) (fp16)
__device__ __align__(16) __half g_h2l[(size_t)NN * C2];   // h2 @ W2 (fp16)
__device__ __align__(16) float g_als1[NN * HEADS];
__device__ __align__(16) float g_ald1[NN * HEADS];
__device__ float g_als2[NN];
__device__ float g_ald2[NN];
__device__ int   g_cnt[NN];
__device__ int   g_off[NN + 1];
__device__ int   g_cur[NN];
__device__ int   g_psrc[ET];
__device__ int   g_bsum[256];
__device__ __align__(16) __half g_w1h[128 * C1];   // [k=128][n=256]
__device__ __align__(16) __half g_w2h[C1 * C2];    // [k=256][n=64]

__device__ __forceinline__ float lrelu(float x) { return x > 0.f ? x : NEG * x; }
__device__ __forceinline__ float elu_f(float x) { return x > 0.f ? x : __expf(x) - 1.f; }

__device__ __forceinline__ void cp16z(uint32_t d, const void* s, bool pred) {
  if (pred)
    asm volatile("cp.async.ca.shared.global [%0], [%1], 16;" :: "r"(d), "l"(s));
  else
    asm volatile("cp.async.ca.shared.global [%0], [%1], 16, 0;" :: "r"(d), "l"(s));
}
__device__ __forceinline__ void cpa_commit() {
  asm volatile("cp.async.commit_group;" ::: "memory");
}
template <int N>
__device__ __forceinline__ void cpa_wait() {
  asm volatile("cp.async.wait_group %0;" :: "n"(N) : "memory");
}

// ---------------- CSR build ---------------------------------------------------
__global__ void k_hist(const int* __restrict__ ei) {
  int e = blockIdx.x * blockDim.x + threadIdx.x;
  if (e < EE) atomicAdd(&g_cnt[ei[EE + e]], 1);
}

__global__ __launch_bounds__(256) void k_scan1() {
  int i = blockIdx.x * 256 + threadIdx.x;
  int v = 0;
  if (i < NN) { v = g_cnt[i] + 1; g_cnt[i] = 0; }
  int lane = threadIdx.x & 31, wid = threadIdx.x >> 5;
  int x = v;
#pragma unroll
  for (int o = 1; o < 32; o <<= 1) {
    int y = __shfl_up_sync(0xffffffffu, x, o);
    if (lane >= o) x += y;
  }
  __shared__ int ws[8];
  if (lane == 31) ws[wid] = x;
  __syncthreads();
  if (threadIdx.x < 8) {
    int z = ws[threadIdx.x];
#pragma unroll
    for (int o = 1; o < 8; o <<= 1) {
      int q = __shfl_up_sync(0xffu, z, o);
      if ((int)threadIdx.x >= o) z += q;
    }
    ws[threadIdx.x] = z;
  }
  __syncthreads();
  int incl = x + (wid ? ws[wid - 1] : 0);
  if (i < NN) g_off[i] = incl - v;
  if (threadIdx.x == 255) g_bsum[blockIdx.x] = incl;
}

__global__ __launch_bounds__(256) void k_scan2() {
  const int NB = (NN + 255) / 256;
  int t = threadIdx.x;
  int v = (t < NB) ? g_bsum[t] : 0;
  int lane = t & 31, wid = t >> 5;
  int x = v;
#pragma unroll
  for (int o = 1; o < 32; o <<= 1) {
    int y = __shfl_up_sync(0xffffffffu, x, o);
    if (lane >= o) x += y;
  }
  __shared__ int ws[8];
  if (lane == 31) ws[wid] = x;
  __syncthreads();
  if (t < 8) {
    int z = ws[t];
#pragma unroll
    for (int o = 1; o < 8; o <<= 1) {
      int q = __shfl_up_sync(0xffu, z, o);
      if (t >= o) z += q;
    }
    ws[t] = z;
  }
  __syncthreads();
  int incl = x + (wid ? ws[wid - 1] : 0);
  if (t < NB) g_bsum[t] = incl - v;
}

__global__ void k_scan3() {
  int i = blockIdx.x * blockDim.x + threadIdx.x;
  if (i < NN) {
    int o = g_off[i] + g_bsum[i >> 8];
    g_off[i] = o;
    g_psrc[o] = i;
    g_cur[i] = o + 1;
  }
  if (i == 0) g_off[NN] = ET;
}

__global__ void k_scatter(const int* __restrict__ ei) {
  int e = blockIdx.x * blockDim.x + threadIdx.x;
  if (e < EE) {
    int s = ei[e];
    int d = ei[EE + e];
    g_psrc[atomicAdd(&g_cur[d], 1)] = s;
  }
}

// ---------------- conversions (x + W1 + W2, one kernel) -------------------------
__global__ void k_cvt(const float* __restrict__ x, const float* __restrict__ W1,
                      const float* __restrict__ W2) {
  int i = blockIdx.x * blockDim.x + threadIdx.x;   // 8-elem chunk index
  const int n8 = NN * 128 / 8;
  if (i < n8) {
    float4 v0 = __ldg((const float4*)x + 2 * i);
    float4 v1 = __ldg((const float4*)x + 2 * i + 1);
    union Pk { __half h[8]; uint4 u; } pk;
    pk.h[0] = __float2half_rn(v0.x); pk.h[1] = __float2half_rn(v0.y);
    pk.h[2] = __float2half_rn(v0.z); pk.h[3] = __float2half_rn(v0.w);
    pk.h[4] = __float2half_rn(v1.x); pk.h[5] = __float2half_rn(v1.y);
    pk.h[6] = __float2half_rn(v1.z); pk.h[7] = __float2half_rn(v1.w);
    ((uint4*)g_xh)[i] = pk.u;
  }
  if (i < 128 * 256) g_w1h[i] = __float2half_rn(__ldg(&W1[i]));
  if (i < 256 * 64)  g_w2h[i] = __float2half_rn(__ldg(&W2[i]));
}

// ---------------- wmma GEMM (fp16 x fp16, fp32 accum, all-cp.async) ------------
template <int MODE>
__global__ __launch_bounds__(256, 2) void k_wgemm(const float* __restrict__ avs,
                                                  const float* __restrict__ avd,
                                                  int bmb) {
  constexpr int K  = (MODE == 1) ? 128 : 256;
  constexpr int NC = (MODE == 1) ? 256 : 64;
  constexpr int BN = (MODE == 1) ? 128 : 64;
  constexpr int BM = 128, BK = 32;
  constexpr int KT = K / BK;
  constexpr int LDA = 40;         // 80 B rows — conflict-free
  constexpr int LDB = BN + 8;     // 272/144 B rows — conflict-free
  constexpr int NJ = BN / 32;
  constexpr int ASTG = BM * LDA;
  constexpr int BSTG = BK * LDB;
  constexpr int LDC = BN + 4;

  extern __shared__ __half sm[];
  __half* Ah = sm;                      // [2][ASTG]
  __half* Bh = Ah + 2 * ASTG;           // [2][BSTG]
  float* Ct = (float*)sm;               // overlay after MMA

  const __half* Ag = (MODE == 1) ? g_xh : g_h2h;
  const __half* Bg = (MODE == 1) ? g_w1h : g_w2h;

  const int tid = threadIdx.x;
  const int wid = tid >> 5;
  const int lane = tid & 31;
  const int wr = wid >> 1, wc = wid & 1;
  const int bm = (blockIdx.x + bmb) * BM;
  const int bn = blockIdx.y * BN;

  auto loadA = [&](int kt, int st) {
#pragma unroll
    for (int it = 0; it < 2; it++) {
      int v = it * 256 + tid;
      int r = v >> 2, c8 = (v & 3) << 3;
      int gr = bm + r;
      bool ok = gr < NN;
      size_t go = (size_t)(ok ? gr : 0) * K + kt * BK + c8;
      cp16z((uint32_t)__cvta_generic_to_shared(&Ah[st * ASTG + r * LDA + c8]),
            Ag + go, ok);
    }
  };
  auto loadB = [&](int kt, int st) {
    constexpr int NV = BK * BN / 8;
#pragma unroll
    for (int it = 0; it < NV / 256; it++) {
      int v = it * 256 + tid;
      int r = v / (BN / 8), c8 = (v % (BN / 8)) << 3;
      size_t go = (size_t)(kt * BK + r) * NC + bn + c8;
      cp16z((uint32_t)__cvta_generic_to_shared(&Bh[st * BSTG + r * LDB + c8]),
            Bg + go, true);
    }
  };

  wmma::fragment<wmma::accumulator, 16, 16, 16, float> acc[2][NJ];
#pragma unroll
  for (int i = 0; i < 2; i++)
#pragma unroll
    for (int j = 0; j < NJ; j++) wmma::fill_fragment(acc[i][j], 0.f);

  loadA(0, 0); loadB(0, 0); cpa_commit();
  cpa_wait<0>();
  __syncthreads();

#pragma unroll
  for (int kt = 0; kt < KT; kt++) {
    const int cur = kt & 1;
    const bool pre = (kt + 1 < KT);
    if (pre) { loadA(kt + 1, cur ^ 1); loadB(kt + 1, cur ^ 1); cpa_commit(); }
#pragma unroll
    for (int kk = 0; kk < BK; kk += 16) {
      wmma::fragment<wmma::matrix_a, 16, 16, 16, __half, wmma::row_major> fa[2];
#pragma unroll
      for (int i = 0; i < 2; i++)
        wmma::load_matrix_sync(fa[i], &Ah[cur * ASTG + (wr * 32 + i * 16) * LDA + kk], LDA);
#pragma unroll
      for (int j = 0; j < NJ; j++) {
        wmma::fragment<wmma::matrix_b, 16, 16, 16, __half, wmma::row_major> fb;
        wmma::load_matrix_sync(fb, &Bh[cur * BSTG + kk * LDB + wc * NJ * 16 + j * 16], LDB);
        wmma::mma_sync(acc[0][j], fa[0], fb, acc[0][j]);
        wmma::mma_sync(acc[1][j], fa[1], fb, acc[1][j]);
      }
    }
    if (pre) cpa_wait<0>();
    __syncthreads();
  }

#pragma unroll
  for (int i = 0; i < 2; i++)
#pragma unroll
    for (int j = 0; j < NJ; j++)
      wmma::store_matrix_sync(&Ct[(wr * 32 + i * 16) * LDC + wc * NJ * 16 + j * 16],
                              acc[i][j], LDC, wmma::mem_row_major);
  __syncthreads();

  // write C as fp16 (g_h1h for MODE1, g_h2l for MODE2)
  {
    __half* dst = (MODE == 1) ? g_h1h : g_h2l;
    constexpr int NV8 = BM * BN / 8;
    for (int v = tid; v < NV8; v += 256) {
      int r = v / (BN / 8), c8 = (v % (BN / 8)) << 3;
      if (bm + r < NN) {
        const float* src = &Ct[r * LDC + c8];
        union Pk { __half h[8]; uint4 u; } pk;
#pragma unroll
        for (int e = 0; e < 8; e++) pk.h[e] = __float2half_rn(src[e]);
        *(uint4*)&dst[(size_t)(bm + r) * NC + bn + c8] = pk.u;
      }
    }
  }

  const int rl = wid * 16 + (lane >> 1);
  const int hl = lane & 1;
  const int row = bm + rl;
  if constexpr (MODE == 1) {
    if (row < NN) {
      const float* cr = &Ct[rl * LDC + hl * 64];
      const float* va2 = avs + (blockIdx.y * 2 + hl) * 64;
      const float* vd2 = avd + (blockIdx.y * 2 + hl) * 64;
      float ss = 0.f, dd = 0.f;
#pragma unroll
      for (int t = 0; t < 64; t += 4) {
        float4 c = *(const float4*)(cr + t);
        float4 a = __ldg((const float4*)(va2 + t));
        float4 d = __ldg((const float4*)(vd2 + t));
        ss += c.x * a.x + c.y * a.y + c.z * a.z + c.w * a.w;
        dd += c.x * d.x + c.y * d.y + c.z * d.z + c.w * d.w;
      }
      g_als1[row * 4 + blockIdx.y * 2 + hl] = ss;
      g_ald1[row * 4 + blockIdx.y * 2 + hl] = dd;
    }
  } else {
    const float* cr = &Ct[rl * LDC + hl * 32];
    float ss = 0.f, dd = 0.f;
#pragma unroll
    for (int t = 0; t < 32; t += 4) {
      float4 c = *(const float4*)(cr + t);
      float4 a = __ldg((const float4*)(avs + hl * 32 + t));
      float4 d = __ldg((const float4*)(avd + hl * 32 + t));
      ss += c.x * a.x + c.y * a.y + c.z * a.z + c.w * a.w;
      dd += c.x * d.x + c.y * d.y + c.z * d.z + c.w * d.w;
    }
    ss += __shfl_xor_sync(0xffffffffu, ss, 1);
    dd += __shfl_xor_sync(0xffffffffu, dd, 1);
    if (hl == 0 && row < NN) {
      g_als2[row] = ss;
      g_ald2[row] = dd;
    }
  }
}

// ---------------- layer1 aggregation: warp per dst node (R15 structure) -------
__global__ __launch_bounds__(256) void k_agg1(const float* __restrict__ b1,
                                              int n0, int n1) {
  int w = n0 + ((blockIdx.x * 256 + threadIdx.x) >> 5);
  int lane = threadIdx.x & 31;
  if (w >= n1) return;
  const int node = w;
  const int off = g_off[node], end = g_off[node + 1];
  float4 ad = *(const float4*)&g_ald1[node * 4];

  float m0 = -3e38f, m1 = -3e38f, m2 = -3e38f, m3 = -3e38f;
  float s0 = 0.f, s1 = 0.f, s2 = 0.f, s3 = 0.f;
  for (int j = off + lane; j < end; j += 32) {
    int s = g_psrc[j];
    float4 as = __ldg((const float4*)&g_als1[s * 4]);
    float e0 = lrelu(as.x + ad.x), e1 = lrelu(as.y + ad.y);
    float e2 = lrelu(as.z + ad.z), e3 = lrelu(as.w + ad.w);
    float n0_ = fmaxf(m0, e0), n1_ = fmaxf(m1, e1);
    float n2_ = fmaxf(m2, e2), n3_ = fmaxf(m3, e3);
    s0 = s0 * __expf(m0 - n0_) + __expf(e0 - n0_); m0 = n0_;
    s1 = s1 * __expf(m1 - n1_) + __expf(e1 - n1_); m1 = n1_;
    s2 = s2 * __expf(m2 - n2_) + __expf(e2 - n2_); m2 = n2_;
    s3 = s3 * __expf(m3 - n3_) + __expf(e3 - n3_); m3 = n3_;
  }
  float lm0 = m0, lm1 = m1, lm2 = m2, lm3 = m3;
#pragma unroll
  for (int o = 16; o; o >>= 1) {
    m0 = fmaxf(m0, __shfl_xor_sync(0xffffffffu, m0, o));
    m1 = fmaxf(m1, __shfl_xor_sync(0xffffffffu, m1, o));
    m2 = fmaxf(m2, __shfl_xor_sync(0xffffffffu, m2, o));
    m3 = fmaxf(m3, __shfl_xor_sync(0xffffffffu, m3, o));
  }
  s0 *= __expf(lm0 - m0);
  s1 *= __expf(lm1 - m1);
  s2 *= __expf(lm2 - m2);
  s3 *= __expf(lm3 - m3);
#pragma unroll
  for (int o = 16; o; o >>= 1) {
    s0 += __shfl_xor_sync(0xffffffffu, s0, o);
    s1 += __shfl_xor_sync(0xffffffffu, s1, o);
    s2 += __shfl_xor_sync(0xffffffffu, s2, o);
    s3 += __shfl_xor_sync(0xffffffffu, s3, o);
  }
  const int hd = lane >> 3;
  float mh = hd == 0 ? m0 : hd == 1 ? m1 : hd == 2 ? m2 : m3;
  float sh = hd == 0 ? s0 : hd == 1 ? s1 : hd == 2 ? s2 : s3;
  float adh = hd == 0 ? ad.x : hd == 1 ? ad.y : hd == 2 ? ad.z : ad.w;
  float inv = 1.f / (sh + 1e-16f);

  float acc[8] = {0.f, 0.f, 0.f, 0.f, 0.f, 0.f, 0.f, 0.f};
  const int myc = lane << 3;
  int j = off;
  int sA = 0, sB = 0;
  if (j + 2 <= end) { sA = g_psrc[j]; sB = g_psrc[j + 1]; }
  while (j + 2 <= end) {
    int nA = sA, nB = sB;
    if (j + 4 <= end) { nA = g_psrc[j + 2]; nB = g_psrc[j + 3]; }
    float aA = __ldg(&g_als1[sA * 4 + hd]);
    float aB = __ldg(&g_als1[sB * 4 + hd]);
    uint4 uA = __ldg((const uint4*)(g_h1h + (size_t)sA * C1 + myc));
    uint4 uB = __ldg((const uint4*)(g_h1h + (size_t)sB * C1 + myc));
    float alA = __expf(lrelu(aA + adh) - mh) * inv;
    float alB = __expf(lrelu(aB + adh) - mh) * inv;
    const __half2* hA = (const __half2*)&uA;
    const __half2* hB = (const __half2*)&uB;
#pragma unroll
    for (int q = 0; q < 4; q++) {
      float2 fA = __half22float2(hA[q]);
      float2 fB = __half22float2(hB[q]);
      acc[2 * q]     += fA.x * alA + fB.x * alB;
      acc[2 * q + 1] += fA.y * alA + fB.y * alB;
    }
    j += 2; sA = nA; sB = nB;
  }
  if (j < end) {
    int s = g_psrc[j];
    float asv = __ldg(&g_als1[s * 4 + hd]);
    float alpha = __expf(lrelu(asv + adh) - mh) * inv;
    uint4 u = __ldg((const uint4*)(g_h1h + (size_t)s * C1 + myc));
    const __half2* hh = (const __half2*)&u;
#pragma unroll
    for (int q = 0; q < 4; q++) {
      float2 f = __half22float2(hh[q]);
      acc[2 * q]     += f.x * alpha;
      acc[2 * q + 1] += f.y * alpha;
    }
  }
  float4 bb0 = __ldg((const float4*)&b1[myc]);
  float4 bb1 = __ldg((const float4*)&b1[myc + 4]);
  float vo[8];
  vo[0] = elu_f(acc[0] + bb0.x); vo[1] = elu_f(acc[1] + bb0.y);
  vo[2] = elu_f(acc[2] + bb0.z); vo[3] = elu_f(acc[3] + bb0.w);
  vo[4] = elu_f(acc[4] + bb1.x); vo[5] = elu_f(acc[5] + bb1.y);
  vo[6] = elu_f(acc[6] + bb1.z); vo[7] = elu_f(acc[7] + bb1.w);
  union Pk { __half h[8]; uint4 u; } ph;
#pragma unroll
  for (int e = 0; e < 8; e++) ph.h[e] = __float2half_rn(vo[e]);
  *(uint4*)&g_h2h[(size_t)node * C1 + myc] = ph.u;
}

// ---------------- layer2 aggregation: warp per dst node (fp16 gather) ---------
__global__ __launch_bounds__(256) void k_agg2(const float* __restrict__ b2,
                                              float* __restrict__ out) {
  int w = (blockIdx.x * 256 + threadIdx.x) >> 5;
  int lane = threadIdx.x & 31;
  if (w >= NN) return;
  const int node = w;
  const int off = g_off[node], end = g_off[node + 1];
  float ad = g_ald2[node];

  float m = -3e38f, su = 0.f;
  for (int j = off + lane; j < end; j += 32) {
    int s = g_psrc[j];
    float e = lrelu(__ldg(&g_als2[s]) + ad);
    float nm = fmaxf(m, e);
    su = su * __expf(m - nm) + __expf(e - nm); m = nm;
  }
  float lm = m;
#pragma unroll
  for (int o = 16; o; o >>= 1)
    m = fmaxf(m, __shfl_xor_sync(0xffffffffu, m, o));
  su *= __expf(lm - m);
#pragma unroll
  for (int o = 16; o; o >>= 1)
    su += __shfl_xor_sync(0xffffffffu, su, o);
  float inv = 1.f / (su + 1e-16f);

  float a0 = 0.f, a1 = 0.f;
  const int c = lane << 1;
  int j = off;
  int sA = 0, sB = 0;
  if (j + 2 <= end) { sA = g_psrc[j]; sB = g_psrc[j + 1]; }
  while (j + 2 <= end) {
    int nA = sA, nB = sB;
    if (j + 4 <= end) { nA = g_psrc[j + 2]; nB = g_psrc[j + 3]; }
    float eA = __ldg(&g_als2[sA]), eB = __ldg(&g_als2[sB]);
    float2 pA = __half22float2(__ldg((const __half2*)(g_h2l + (size_t)sA * C2 + c)));
    float2 pB = __half22float2(__ldg((const __half2*)(g_h2l + (size_t)sB * C2 + c)));
    float alA = __expf(lrelu(eA + ad) - m) * inv;
    float alB = __expf(lrelu(eB + ad) - m) * inv;
    a0 += pA.x * alA + pB.x * alB;
    a1 += pA.y * alA + pB.y * alB;
    j += 2; sA = nA; sB = nB;
  }
  if (j < end) {
    int s = g_psrc[j];
    float alpha = __expf(lrelu(__ldg(&g_als2[s]) + ad) - m) * inv;
    float2 p = __half22float2(__ldg((const __half2*)(g_h2l + (size_t)s * C2 + c)));
    a0 += p.x * alpha;
    a1 += p.y * alpha;
  }
  float2 r;
  r.x = elu_f(a0 + __ldg(&b2[c]));
  r.y = elu_f(a1 + __ldg(&b2[c + 1]));
  *(float2*)(out + (size_t)node * C2 + c) = r;
}

// ---------------- launch ------------------------------------------------------
extern "C" void kernel_launch(void* const* d_in, const int* in_sizes, int n_in,
                              void* d_out, int out_size) {
  const float* x = (const float*)d_in[0];
  const int* ei = (const int*)d_in[1];
  const float* W1 = (const float*)d_in[2];
  const float* as1 = (const float*)d_in[3];
  const float* ad1 = (const float*)d_in[4];
  const float* b1 = (const float*)d_in[5];
  const float* W2 = (const float*)d_in[6];
  const float* as2 = (const float*)d_in[7];
  const float* ad2 = (const float*)d_in[8];
  const float* b2 = (const float*)d_in[9];
  float* out = (float*)d_out;

  static cudaStream_t s_csr = nullptr;
  static cudaEvent_t ev_fork = nullptr, ev_join = nullptr, ev_a0 = nullptr,
                     ev_w0 = nullptr;
  if (!s_csr) {
    cudaStreamCreateWithFlags(&s_csr, cudaStreamNonBlocking);
    cudaEventCreateWithFlags(&ev_fork, cudaEventDisableTiming);
    cudaEventCreateWithFlags(&ev_join, cudaEventDisableTiming);
    cudaEventCreateWithFlags(&ev_a0, cudaEventDisableTiming);
    cudaEventCreateWithFlags(&ev_w0, cudaEventDisableTiming);
  }

  // smem = max(pipeline, C-tile overlay)
  const int PIPE1 = (2 * 128 * 40 + 2 * 32 * 136) * 2;  // 37888 B
  const int CT1 = 128 * (128 + 4) * 4;                  // 67584 B
  const int SMEM1 = PIPE1 > CT1 ? PIPE1 : CT1;
  const int PIPE2 = (2 * 128 * 40 + 2 * 32 * 72) * 2;   // 29696 B
  const int CT2 = 128 * (64 + 4) * 4;                   // 34816 B
  const int SMEM2 = PIPE2 > CT2 ? PIPE2 : CT2;
  cudaFuncSetAttribute(k_wgemm<1>, cudaFuncAttributeMaxDynamicSharedMemorySize, SMEM1);
  cudaFuncSetAttribute(k_wgemm<2>, cudaFuncAttributeMaxDynamicSharedMemorySize, SMEM2);

  const int NB = (NN + 255) / 256;  // 196
  const int NT = (NN + 127) / 128;  // 391
  const int NT0 = CH / 128;         // 196
  const int NT1 = NT - NT0;         // 195

  cudaEventRecord(ev_fork, 0);
  cudaStreamWaitEvent(s_csr, ev_fork, 0);

  // submission order: idx 3 = k_wgemm<1> (profiler captures 4th kernel)
  k_cvt<<<(NN * 128 / 8 + 255) / 256, 256>>>(x, W1, W2);        // s0, idx 0
  k_hist<<<(EE + 255) / 256, 256, 0, s_csr>>>(ei);              // idx 1
  k_scan1<<<NB, 256, 0, s_csr>>>();                             // idx 2
  dim3 g1(NT, C1 / 128);
  k_wgemm<1><<<g1, 256, SMEM1>>>(as1, ad1, 0);                  // s0, idx 3
  k_scan2<<<1, 256, 0, s_csr>>>();                              // idx 4
  k_scan3<<<NB, 256, 0, s_csr>>>();                             // idx 5
  k_scatter<<<(EE + 255) / 256, 256, 0, s_csr>>>(ei);           // idx 6
  cudaEventRecord(ev_join, s_csr);

  cudaStreamWaitEvent(0, ev_join, 0);
  k_agg1<<<CH * 32 / 256, 256>>>(b1, 0, CH);                    // chunk 0
  cudaEventRecord(ev_a0, 0);
  k_agg1<<<((NN - CH) * 32 + 255) / 256, 256>>>(b1, CH, NN);    // chunk 1

  cudaStreamWaitEvent(s_csr, ev_a0, 0);
  k_wgemm<2><<<NT0, 256, SMEM2, s_csr>>>(as2, ad2, 0);
  cudaEventRecord(ev_w0, s_csr);

  k_wgemm<2><<<NT1, 256, SMEM2>>>(as2, ad2, NT0);

  cudaStreamWaitEvent(0, ev_w0, 0);
  int nwb = (NN * 32 + 255) / 256;
  k_agg2<<<nwb, 256>>>(b2, out);
}